// round 10
// baseline (speedup 1.0000x reference)
#include <cuda_runtime.h>
#include <cuda_bf16.h>
#include <math.h>

#define HEADS 8
#define CDIM  256
#define NTOK  4096
#define BATCH 2
#define DK    32
#define MROWS (BATCH * NTOK)   // 8192

#define QSCALE 0.25500526114838825f

// Scratch (no allocations allowed)
__device__ __nv_bfloat16 g_tok[BATCH * NTOK * CDIM];
__device__ __nv_bfloat16 g_wqkv_hi[3 * CDIM * CDIM];
__device__ __nv_bfloat16 g_wqkv_lo[3 * CDIM * CDIM];
__device__ float         g_bias[3 * CDIM];
__device__ __nv_bfloat16 g_q[BATCH * HEADS * NTOK * DK];
__device__ __nv_bfloat16 g_k[BATCH * HEADS * NTOK * DK];
__device__ __nv_bfloat16 g_vt[BATCH * HEADS * DK * NTOK];
__device__ __nv_bfloat16 g_att_hi[BATCH * NTOK * CDIM];
__device__ __nv_bfloat16 g_att_lo[BATCH * NTOK * CDIM];

__device__ __forceinline__ unsigned pack_bf16(float a, float b) {
    __nv_bfloat162 t = __float22bfloat162_rn(make_float2(a, b));
    return *(unsigned*)&t;
}
__device__ __forceinline__ void split_bf16(float v, __nv_bfloat16& hi, __nv_bfloat16& lo) {
    hi = __float2bfloat16(v);
    lo = __float2bfloat16(v - __bfloat162float(hi));
}
__device__ __forceinline__ unsigned ex2_bf16x2(unsigned s) {
    unsigned r;
    asm volatile("ex2.approx.ftz.bf16x2 %0, %1;\n" : "=r"(r) : "r"(s));
    return r;
}
__device__ __forceinline__ void cp_async16(void* smem_dst, const void* gsrc) {
    unsigned saddr = (unsigned)__cvta_generic_to_shared(smem_dst);
    asm volatile("cp.async.ca.shared.global [%0], [%1], 16;\n" :: "r"(saddr), "l"(gsrc));
}
__device__ __forceinline__ void cp_commit() {
    asm volatile("cp.async.commit_group;\n");
}
__device__ __forceinline__ void mma16816(float c[4], const unsigned a[4], const unsigned b[2]) {
    asm volatile(
        "mma.sync.aligned.m16n8k16.row.col.f32.bf16.bf16.f32 "
        "{%0,%1,%2,%3}, {%4,%5,%6,%7}, {%8,%9}, {%0,%1,%2,%3};\n"
        : "+f"(c[0]), "+f"(c[1]), "+f"(c[2]), "+f"(c[3])
        : "r"(a[0]), "r"(a[1]), "r"(a[2]), "r"(a[3]), "r"(b[0]), "r"(b[1]));
}

// ---------------------------------------------------------------------------
// Kernel 1: tok = x + PE (bf16). Coalesced both sides.
// ---------------------------------------------------------------------------
__global__ __launch_bounds__(256) void pe_tok_kernel(const float* __restrict__ x) {
    int n_lo   = threadIdx.x & 31;
    int oct_lo = threadIdx.x >> 5;
    int n_hi   = blockIdx.x & 127;
    int oct_hi = (blockIdx.x >> 7) & 3;
    int b = blockIdx.x >> 9;

    int n = n_hi * 32 + n_lo;
    int ch0 = (oct_hi * 8 + oct_lo) * 8;
    int yy = n >> 6;
    int xx = n & 63;

    __nv_bfloat16 vh[8];
#pragma unroll
    for (int j = 0; j < 8; j++) {
        int ch = ch0 + j;
        int i, pos;
        if (ch < 128) { i = ch >> 1;         pos = xx; }
        else          { i = (ch - 128) >> 1; pos = yy; }
        float div = __expf(-(float)(2 * i) * (9.210340371976184f / 128.0f));
        float arg = (float)pos * div;
        float pe  = (ch & 1) ? cosf(arg) : sinf(arg);
        vh[j] = __float2bfloat16(x[((size_t)(b * CDIM + ch)) * NTOK + n] + pe);
    }
    *(uint4*)&g_tok[((size_t)(b * NTOK) + n) * CDIM + ch0] = *(uint4*)vh;
}

// ---------------------------------------------------------------------------
// Kernel 2: split Wq/Wk/Wv into bf16 hi/lo and gather biases.
// ---------------------------------------------------------------------------
__global__ __launch_bounds__(256) void split_w_kernel(const float* __restrict__ Wq,
                                                      const float* __restrict__ Wk,
                                                      const float* __restrict__ Wv,
                                                      const float* __restrict__ bq,
                                                      const float* __restrict__ bk,
                                                      const float* __restrict__ bv) {
    int t = blockIdx.x * 256 + threadIdx.x;      // 0..49151
    int idx4 = t * 4;
    int w = idx4 >> 16;
    const float* src = (w == 0) ? Wq : (w == 1) ? Wk : Wv;
    float4 v = *(const float4*)&src[idx4 & 65535];
    __nv_bfloat16 h[4], l[4];
    split_bf16(v.x, h[0], l[0]); split_bf16(v.y, h[1], l[1]);
    split_bf16(v.z, h[2], l[2]); split_bf16(v.w, h[3], l[3]);
    *(uint2*)&g_wqkv_hi[idx4] = *(uint2*)h;
    *(uint2*)&g_wqkv_lo[idx4] = *(uint2*)l;
    if (t < 768) {
        int which = t >> 8;
        const float* bsrc = (which == 0) ? bq : (which == 1) ? bk : bv;
        g_bias[t] = bsrc[t & 255];
    }
}

// ---------------------------------------------------------------------------
// Fused QKV GEMM: C = tok(bf16) @ (Wh + Wl)^T + bias  (2-term split-weight).
// (Proven R7 kernel, unchanged.)
// ---------------------------------------------------------------------------
#define GPAD 40

__global__ __launch_bounds__(256) void qkv_mma_kernel() {
    __shared__ __align__(16) __nv_bfloat16 As[2][128][GPAD];
    __shared__ __align__(16) __nv_bfloat16 BsH[2][64][GPAD];
    __shared__ __align__(16) __nv_bfloat16 BsL[2][64][GPAD];

    int tid  = threadIdx.x;
    int warp = tid >> 5;
    int lane = tid & 31;
    int wm   = warp >> 1;
    int wn   = warp & 1;
    int g    = lane >> 2;
    int tig  = lane & 3;
    int m0 = blockIdx.x * 128;
    int w  = blockIdx.y >> 2;
    int o0 = (blockIdx.y & 3) * 64;
    size_t w_off = (size_t)w * 65536 + (size_t)o0 * CDIM;

    float c[2][4][4] = {};

    auto stage = [&](int s, int k0) {
#pragma unroll
        for (int i = 0; i < 2; i++) {
            int idx = tid * 2 + i;
            int row = idx >> 2, c8 = (idx & 3) * 8;
            cp_async16(&As[s][row][c8], g_tok + (size_t)(m0 + row) * CDIM + k0 + c8);
        }
        {
            int row = tid >> 2, c8 = (tid & 3) * 8;
            size_t go = w_off + (size_t)row * CDIM + k0 + c8;
            cp_async16(&BsH[s][row][c8], g_wqkv_hi + go);
            cp_async16(&BsL[s][row][c8], g_wqkv_lo + go);
        }
        cp_commit();
    };

    stage(0, 0);

#pragma unroll
    for (int it = 0; it < 8; it++) {
        int s = it & 1;
        asm volatile("cp.async.wait_group 0;\n");
        __syncthreads();
        if (it < 7) stage(s ^ 1, (it + 1) * 32);

        unsigned af[2][2][4];
        unsigned bfH[4][2][2], bfL[4][2][2];
#pragma unroll
        for (int mt = 0; mt < 2; mt++) {
            int r = wm * 32 + mt * 16 + g;
            const unsigned* h0 = (const unsigned*)&As[s][r][0];
            const unsigned* h1 = (const unsigned*)&As[s][r + 8][0];
#pragma unroll
            for (int kc = 0; kc < 2; kc++) {
                af[mt][kc][0] = h0[kc * 8 + tig];
                af[mt][kc][1] = h1[kc * 8 + tig];
                af[mt][kc][2] = h0[kc * 8 + tig + 4];
                af[mt][kc][3] = h1[kc * 8 + tig + 4];
            }
        }
#pragma unroll
        for (int nt = 0; nt < 4; nt++) {
            int r = wn * 32 + nt * 8 + g;
            const unsigned* rh = (const unsigned*)&BsH[s][r][0];
            const unsigned* rl = (const unsigned*)&BsL[s][r][0];
#pragma unroll
            for (int kc = 0; kc < 2; kc++) {
                bfH[nt][kc][0] = rh[kc * 8 + tig];
                bfH[nt][kc][1] = rh[kc * 8 + tig + 4];
                bfL[nt][kc][0] = rl[kc * 8 + tig];
                bfL[nt][kc][1] = rl[kc * 8 + tig + 4];
            }
        }

#pragma unroll
        for (int mt = 0; mt < 2; mt++)
#pragma unroll
            for (int nt = 0; nt < 4; nt++)
#pragma unroll
                for (int kc = 0; kc < 2; kc++) {
                    mma16816(c[mt][nt], af[mt][kc], bfH[nt][kc]);
                    mma16816(c[mt][nt], af[mt][kc], bfL[nt][kc]);
                }
    }

#pragma unroll
    for (int mt = 0; mt < 2; mt++) {
        int row0 = m0 + wm * 32 + mt * 16 + g;
#pragma unroll
        for (int nt = 0; nt < 4; nt++) {
            int o  = o0 + wn * 32 + nt * 8 + 2 * tig;
            float b0 = g_bias[w * 256 + o];
            float b1 = g_bias[w * 256 + o + 1];
#pragma unroll
            for (int half = 0; half < 2; half++) {
                int row = row0 + half * 8;
                int b = row >> 12;
                int n = row & 4095;
                float v0 = c[mt][nt][2 * half + 0] + b0;
                float v1 = c[mt][nt][2 * half + 1] + b1;
                if (w == 0) {
                    *(unsigned*)&g_q[(((size_t)(b * HEADS + (o >> 5))) * NTOK + n) * DK + (o & 31)] =
                        pack_bf16(v0 * QSCALE, v1 * QSCALE);
                } else if (w == 1) {
                    *(unsigned*)&g_k[(((size_t)(b * HEADS + (o >> 5))) * NTOK + n) * DK + (o & 31)] =
                        pack_bf16(v0, v1);
                } else {
                    __nv_bfloat16* base = g_vt +
                        ((size_t)(b * HEADS + (o >> 5))) * DK * NTOK + n;
                    base[(size_t)(o & 31) * NTOK]       = __float2bfloat16(v0);
                    base[(size_t)((o & 31) + 1) * NTOK] = __float2bfloat16(v1);
                }
            }
        }
    }
}

// ---------------------------------------------------------------------------
// Output projection: split-bf16 (hi/lo both operands) — proven R4 kernel.
// ---------------------------------------------------------------------------
__global__ __launch_bounds__(256) void gemm_o_kernel(const __nv_bfloat16* __restrict__ Ah,
                                                     const __nv_bfloat16* __restrict__ Al,
                                                     const float* __restrict__ W,
                                                     const float* __restrict__ bias,
                                                     float* __restrict__ Cout) {
    __shared__ __nv_bfloat16 AsH[128][GPAD];
    __shared__ __nv_bfloat16 AsL[128][GPAD];
    __shared__ __nv_bfloat16 BsH[64][GPAD];
    __shared__ __nv_bfloat16 BsL[64][GPAD];

    int tid  = threadIdx.x;
    int warp = tid >> 5;
    int lane = tid & 31;
    int wm   = warp >> 1;
    int wn   = warp & 1;
    int g    = lane >> 2;
    int tig  = lane & 3;
    int m0 = blockIdx.x * 128;
    int o0 = blockIdx.y * 64;

    float c[2][4][4] = {};

    uint4  ah_reg[2], al_reg[2];
    float4 w_reg[2];

    auto ldg_stage = [&](int k0) {
#pragma unroll
        for (int i = 0; i < 2; i++) {
            int idx = tid + i * 256;
            size_t aoff = ((size_t)(m0 + (idx >> 2))) * CDIM + k0 + (idx & 3) * 8;
            ah_reg[i] = *(const uint4*)&Ah[aoff];
            al_reg[i] = *(const uint4*)&Al[aoff];
            w_reg[i]  = *(const float4*)&W[((size_t)(o0 + (idx >> 3))) * CDIM + k0 + (idx & 7) * 4];
        }
    };
    auto sts_stage = [&]() {
#pragma unroll
        for (int i = 0; i < 2; i++) {
            int idx = tid + i * 256;
            *(uint4*)&AsH[idx >> 2][(idx & 3) * 8] = ah_reg[i];
            *(uint4*)&AsL[idx >> 2][(idx & 3) * 8] = al_reg[i];
            float w[4] = {w_reg[i].x, w_reg[i].y, w_reg[i].z, w_reg[i].w};
            __nv_bfloat16 wh[4], wl[4];
#pragma unroll
            for (int j = 0; j < 4; j++) split_bf16(w[j], wh[j], wl[j]);
            *(uint2*)&BsH[idx >> 3][(idx & 7) * 4] = *(uint2*)wh;
            *(uint2*)&BsL[idx >> 3][(idx & 7) * 4] = *(uint2*)wl;
        }
    };

    ldg_stage(0);
    sts_stage();
    __syncthreads();

#pragma unroll
    for (int it = 0; it < 8; it++) {
        if (it < 7) ldg_stage((it + 1) * 32);

        unsigned afH[2][2][4], afL[2][2][4];
        unsigned bfH[4][2][2], bfL[4][2][2];
#pragma unroll
        for (int mt = 0; mt < 2; mt++) {
            int r = wm * 32 + mt * 16 + g;
            const unsigned* h0 = (const unsigned*)&AsH[r][0];
            const unsigned* h1 = (const unsigned*)&AsH[r + 8][0];
            const unsigned* l0 = (const unsigned*)&AsL[r][0];
            const unsigned* l1 = (const unsigned*)&AsL[r + 8][0];
#pragma unroll
            for (int kc = 0; kc < 2; kc++) {
                afH[mt][kc][0] = h0[kc * 8 + tig];
                afH[mt][kc][1] = h1[kc * 8 + tig];
                afH[mt][kc][2] = h0[kc * 8 + tig + 4];
                afH[mt][kc][3] = h1[kc * 8 + tig + 4];
                afL[mt][kc][0] = l0[kc * 8 + tig];
                afL[mt][kc][1] = l1[kc * 8 + tig];
                afL[mt][kc][2] = l0[kc * 8 + tig + 4];
                afL[mt][kc][3] = l1[kc * 8 + tig + 4];
            }
        }
#pragma unroll
        for (int nt = 0; nt < 4; nt++) {
            int r = wn * 32 + nt * 8 + g;
            const unsigned* rh = (const unsigned*)&BsH[r][0];
            const unsigned* rl = (const unsigned*)&BsL[r][0];
#pragma unroll
            for (int kc = 0; kc < 2; kc++) {
                bfH[nt][kc][0] = rh[kc * 8 + tig];
                bfH[nt][kc][1] = rh[kc * 8 + tig + 4];
                bfL[nt][kc][0] = rl[kc * 8 + tig];
                bfL[nt][kc][1] = rl[kc * 8 + tig + 4];
            }
        }

#pragma unroll
        for (int mt = 0; mt < 2; mt++)
#pragma unroll
            for (int nt = 0; nt < 4; nt++)
#pragma unroll
                for (int kc = 0; kc < 2; kc++) {
                    mma16816(c[mt][nt], afH[mt][kc], bfH[nt][kc]);
                    mma16816(c[mt][nt], afH[mt][kc], bfL[nt][kc]);
                    mma16816(c[mt][nt], afL[mt][kc], bfH[nt][kc]);
                }

        __syncthreads();
        if (it < 7) {
            sts_stage();
            __syncthreads();
        }
    }

#pragma unroll
    for (int mt = 0; mt < 2; mt++) {
        int row0 = m0 + wm * 32 + mt * 16 + g;
#pragma unroll
        for (int nt = 0; nt < 4; nt++) {
            int o  = o0 + wn * 32 + nt * 8 + 2 * tig;
            float b0 = __ldg(&bias[o]);
            float b1 = __ldg(&bias[o + 1]);
#pragma unroll
            for (int half = 0; half < 2; half++) {
                int row = row0 + half * 8;
                int b = row >> 12;
                int n = row & 4095;
                float* base = Cout + (size_t)b * CDIM * NTOK + n;
                base[(size_t)o * NTOK]       = c[mt][nt][2 * half + 0] + b0;
                base[(size_t)(o + 1) * NTOK] = c[mt][nt][2 * half + 1] + b1;
            }
        }
    }
}

// ---------------------------------------------------------------------------
// Flash attention v3: 128 thr / 4 warps, each warp 32 query rows (2 m-tiles
// register-sharing all B fragments). BR=128, BC=64, cp.async S=2, one
// __syncthreads per tile, no online max, bf16x2 exp2, l via ones-MMA.
// ---------------------------------------------------------------------------
#define BR 128
#define BC 64
#define KPAD 40
#define VPAD 72
#define ONES_BF16X2 0x3F803F80u

__global__ __launch_bounds__(128) void flash_mma_kernel() {
    __shared__ __align__(16) __nv_bfloat16 Ks[2][BC][KPAD];
    __shared__ __align__(16) __nv_bfloat16 Vs[2][DK][VPAD];

    int bh    = blockIdx.y;
    int qbase = blockIdx.x * BR;
    int tid   = threadIdx.x;
    int warp  = tid >> 5;
    int lane  = tid & 31;
    int g     = lane >> 2;
    int tig   = lane & 3;

    const __nv_bfloat16* qb = g_q  + (size_t)bh * NTOK * DK;
    const __nv_bfloat16* kb = g_k  + (size_t)bh * NTOK * DK;
    const __nv_bfloat16* vb = g_vt + (size_t)bh * DK * NTOK;

    auto stage_load = [&](int s, int n0) {
#pragma unroll
        for (int i = 0; i < 2; i++) {
            int idx = tid * 2 + i;                       // 0..255
            int kr = idx >> 2, kq = idx & 3;
            cp_async16(&Ks[s][kr][kq * 8], kb + (size_t)(n0 + kr) * DK + kq * 8);
            int vd = idx >> 3, vq = idx & 7;
            cp_async16(&Vs[s][vd][vq * 8], vb + (size_t)vd * NTOK + n0 + vq * 8);
        }
        cp_commit();
    };

    // Q fragments: warp owns 32 rows = 2 m-tiles of 16
    unsigned qf[2][2][4];
    {
#pragma unroll
        for (int mt = 0; mt < 2; mt++) {
            int r0 = qbase + warp * 32 + mt * 16 + g;
            const unsigned* q0 = (const unsigned*)(qb + (size_t)r0 * DK);
            const unsigned* q1 = (const unsigned*)(qb + (size_t)(r0 + 8) * DK);
#pragma unroll
            for (int cc = 0; cc < 2; cc++) {
                qf[mt][cc][0] = q0[8 * cc + tig];
                qf[mt][cc][1] = q1[8 * cc + tig];
                qf[mt][cc][2] = q0[8 * cc + tig + 4];
                qf[mt][cc][3] = q1[8 * cc + tig + 4];
            }
        }
    }

    float O[2][4][4] = {};
    float lacc[2][4] = {};
    const unsigned onesb[2] = {ONES_BF16X2, ONES_BF16X2};

    stage_load(0, 0);

    const int NT = NTOK / BC;
    for (int it = 0; it < NT; it++) {
        int s = it & 1;
        asm volatile("cp.async.wait_group 0;\n");
        __syncthreads();
        if (it + 1 < NT) stage_load(s ^ 1, (it + 1) * BC);

        // Load all K fragments once (shared by both m-tiles)
        unsigned Kf[8][2][2];
#pragma unroll
        for (int t = 0; t < 8; t++) {
            const unsigned* kp = (const unsigned*)&Ks[s][8 * t + g][0];
#pragma unroll
            for (int cc = 0; cc < 2; cc++) {
                Kf[t][cc][0] = kp[8 * cc + tig];
                Kf[t][cc][1] = kp[8 * cc + tig + 4];
            }
        }

        // S = Q@K^T, exp2 per t-group, P fragments for both m-tiles
        unsigned Pf[2][4][4];
#pragma unroll
        for (int mt = 0; mt < 2; mt++) {
#pragma unroll
            for (int t = 0; t < 8; t++) {
                float S4[4] = {0.0f, 0.0f, 0.0f, 0.0f};
                mma16816(S4, qf[mt][0], Kf[t][0]);
                mma16816(S4, qf[mt][1], Kf[t][1]);
                Pf[mt][t >> 1][(t & 1) * 2 + 0] = ex2_bf16x2(pack_bf16(S4[0], S4[1]));
                Pf[mt][t >> 1][(t & 1) * 2 + 1] = ex2_bf16x2(pack_bf16(S4[2], S4[3]));
            }
        }

        // O += P @ V (V fragments loaded once, reused across m-tiles); l += P@1
#pragma unroll
        for (int dt = 0; dt < 4; dt++) {
            const unsigned* vp = (const unsigned*)&Vs[s][8 * dt + g][0];
#pragma unroll
            for (int kc = 0; kc < 4; kc++) {
                unsigned bfr[2];
                bfr[0] = vp[8 * kc + tig];
                bfr[1] = vp[8 * kc + tig + 4];
                mma16816(O[0][dt], Pf[0][kc], bfr);
                mma16816(O[1][dt], Pf[1][kc], bfr);
            }
        }
#pragma unroll
        for (int kc = 0; kc < 4; kc++) {
            mma16816(lacc[0], Pf[0][kc], onesb);
            mma16816(lacc[1], Pf[1][kc], onesb);
        }
    }

    int b = bh >> 3, h = bh & 7;
#pragma unroll
    for (int mt = 0; mt < 2; mt++) {
        float inv0 = 1.0f / lacc[mt][0];
        float inv1 = 1.0f / lacc[mt][2];
        int row0 = qbase + warp * 32 + mt * 16 + g;
        size_t o0off = ((size_t)(b * NTOK + row0) * CDIM) + h * DK;
        size_t o1off = ((size_t)(b * NTOK + row0 + 8) * CDIM) + h * DK;
#pragma unroll
        for (int dt = 0; dt < 4; dt++) {
            int d = 8 * dt + 2 * tig;
            float a0 = O[mt][dt][0] * inv0, a1 = O[mt][dt][1] * inv0;
            float b0 = O[mt][dt][2] * inv1, b1 = O[mt][dt][3] * inv1;
            __nv_bfloat16 h0, l0b, h1, l1b;
            split_bf16(a0, h0, l0b); split_bf16(a1, h1, l1b);
            *(unsigned*)&g_att_hi[o0off + d] = pack_bf16(__bfloat162float(h0), __bfloat162float(h1));
            *(unsigned*)&g_att_lo[o0off + d] = pack_bf16(__bfloat162float(l0b), __bfloat162float(l1b));
            split_bf16(b0, h0, l0b); split_bf16(b1, h1, l1b);
            *(unsigned*)&g_att_hi[o1off + d] = pack_bf16(__bfloat162float(h0), __bfloat162float(h1));
            *(unsigned*)&g_att_lo[o1off + d] = pack_bf16(__bfloat162float(l0b), __bfloat162float(l1b));
        }
    }
}

// ---------------------------------------------------------------------------
extern "C" void kernel_launch(void* const* d_in, const int* in_sizes, int n_in,
                              void* d_out, int out_size) {
    const float* x  = (const float*)d_in[0];
    const float* Wq = (const float*)d_in[1];
    const float* bq = (const float*)d_in[2];
    const float* Wk = (const float*)d_in[3];
    const float* bk = (const float*)d_in[4];
    const float* Wv = (const float*)d_in[5];
    const float* bv = (const float*)d_in[6];
    const float* Wo = (const float*)d_in[7];
    const float* bo = (const float*)d_in[8];
    float* out = (float*)d_out;

    static void *p_att_hi = nullptr, *p_att_lo = nullptr;
    if (!p_att_hi) {
        cudaGetSymbolAddress(&p_att_hi, g_att_hi);
        cudaGetSymbolAddress(&p_att_lo, g_att_lo);
    }

    pe_tok_kernel<<<1024, 256>>>(x);
    split_w_kernel<<<192, 256>>>(Wq, Wk, Wv, bq, bk, bv);

    qkv_mma_kernel<<<dim3(MROWS / 128, 12), 256>>>();

    flash_mma_kernel<<<dim3(NTOK / BR, BATCH * HEADS), 128>>>();

    gemm_o_kernel<<<dim3(MROWS / 128, CDIM / 64), 256>>>(
        (const __nv_bfloat16*)p_att_hi, (const __nv_bfloat16*)p_att_lo, Wo, bo, out);
}

// round 12
// speedup vs baseline: 1.5415x; 1.5415x over previous
#include <cuda_runtime.h>
#include <cuda_bf16.h>
#include <math.h>

#define HEADS 8
#define CDIM  256
#define NTOK  4096
#define BATCH 2
#define DK    32
#define MROWS (BATCH * NTOK)   // 8192

#define QSCALE 0.25500526114838825f

// Scratch (no allocations allowed)
__device__ __nv_bfloat16 g_tok[BATCH * NTOK * CDIM];
__device__ __nv_bfloat16 g_wqkv_hi[3 * CDIM * CDIM];
__device__ __nv_bfloat16 g_wqkv_lo[3 * CDIM * CDIM];
__device__ float         g_bias[3 * CDIM];
__device__ __nv_bfloat16 g_q[BATCH * HEADS * NTOK * DK];
__device__ __nv_bfloat16 g_k[BATCH * HEADS * NTOK * DK];
__device__ __nv_bfloat16 g_vt[BATCH * HEADS * DK * NTOK];
__device__ __nv_bfloat16 g_att_hi[BATCH * NTOK * CDIM];
__device__ __nv_bfloat16 g_att_lo[BATCH * NTOK * CDIM];

__device__ __forceinline__ unsigned pack_bf16(float a, float b) {
    __nv_bfloat162 t = __float22bfloat162_rn(make_float2(a, b));
    return *(unsigned*)&t;
}
__device__ __forceinline__ void split_bf16(float v, __nv_bfloat16& hi, __nv_bfloat16& lo) {
    hi = __float2bfloat16(v);
    lo = __float2bfloat16(v - __bfloat162float(hi));
}
__device__ __forceinline__ unsigned ex2_bf16x2(unsigned s) {
    unsigned r;
    asm volatile("ex2.approx.ftz.bf16x2 %0, %1;\n" : "=r"(r) : "r"(s));
    return r;
}
__device__ __forceinline__ void cp_async16(void* smem_dst, const void* gsrc) {
    unsigned saddr = (unsigned)__cvta_generic_to_shared(smem_dst);
    asm volatile("cp.async.ca.shared.global [%0], [%1], 16;\n" :: "r"(saddr), "l"(gsrc));
}
__device__ __forceinline__ void cp_commit() {
    asm volatile("cp.async.commit_group;\n");
}
__device__ __forceinline__ void mma16816(float c[4], const unsigned a[4], const unsigned b[2]) {
    asm volatile(
        "mma.sync.aligned.m16n8k16.row.col.f32.bf16.bf16.f32 "
        "{%0,%1,%2,%3}, {%4,%5,%6,%7}, {%8,%9}, {%0,%1,%2,%3};\n"
        : "+f"(c[0]), "+f"(c[1]), "+f"(c[2]), "+f"(c[3])
        : "r"(a[0]), "r"(a[1]), "r"(a[2]), "r"(a[3]), "r"(b[0]), "r"(b[1]));
}
__device__ __forceinline__ void ldsm4(unsigned r[4], unsigned saddr) {
    asm volatile("ldmatrix.sync.aligned.m8n8.x4.shared.b16 {%0,%1,%2,%3}, [%4];\n"
                 : "=r"(r[0]), "=r"(r[1]), "=r"(r[2]), "=r"(r[3]) : "r"(saddr));
}

// ---------------------------------------------------------------------------
// Kernel 1: tok = x + PE (bf16). Coalesced both sides.
// ---------------------------------------------------------------------------
__global__ __launch_bounds__(256) void pe_tok_kernel(const float* __restrict__ x) {
    int n_lo   = threadIdx.x & 31;
    int oct_lo = threadIdx.x >> 5;
    int n_hi   = blockIdx.x & 127;
    int oct_hi = (blockIdx.x >> 7) & 3;
    int b = blockIdx.x >> 9;

    int n = n_hi * 32 + n_lo;
    int ch0 = (oct_hi * 8 + oct_lo) * 8;
    int yy = n >> 6;
    int xx = n & 63;

    __nv_bfloat16 vh[8];
#pragma unroll
    for (int j = 0; j < 8; j++) {
        int ch = ch0 + j;
        int i, pos;
        if (ch < 128) { i = ch >> 1;         pos = xx; }
        else          { i = (ch - 128) >> 1; pos = yy; }
        float div = __expf(-(float)(2 * i) * (9.210340371976184f / 128.0f));
        float arg = (float)pos * div;
        float pe  = (ch & 1) ? cosf(arg) : sinf(arg);
        vh[j] = __float2bfloat16(x[((size_t)(b * CDIM + ch)) * NTOK + n] + pe);
    }
    *(uint4*)&g_tok[((size_t)(b * NTOK) + n) * CDIM + ch0] = *(uint4*)vh;
}

// ---------------------------------------------------------------------------
// Kernel 2: split Wq/Wk/Wv into bf16 hi/lo and gather biases.
// ---------------------------------------------------------------------------
__global__ __launch_bounds__(256) void split_w_kernel(const float* __restrict__ Wq,
                                                      const float* __restrict__ Wk,
                                                      const float* __restrict__ Wv,
                                                      const float* __restrict__ bq,
                                                      const float* __restrict__ bk,
                                                      const float* __restrict__ bv) {
    int t = blockIdx.x * 256 + threadIdx.x;      // 0..49151
    int idx4 = t * 4;
    int w = idx4 >> 16;
    const float* src = (w == 0) ? Wq : (w == 1) ? Wk : Wv;
    float4 v = *(const float4*)&src[idx4 & 65535];
    __nv_bfloat16 h[4], l[4];
    split_bf16(v.x, h[0], l[0]); split_bf16(v.y, h[1], l[1]);
    split_bf16(v.z, h[2], l[2]); split_bf16(v.w, h[3], l[3]);
    *(uint2*)&g_wqkv_hi[idx4] = *(uint2*)h;
    *(uint2*)&g_wqkv_lo[idx4] = *(uint2*)l;
    if (t < 768) {
        int which = t >> 8;
        const float* bsrc = (which == 0) ? bq : (which == 1) ? bk : bv;
        g_bias[t] = bsrc[t & 255];
    }
}

// ---------------------------------------------------------------------------
// Fused QKV GEMM: C = tok(bf16) @ (Wh + Wl)^T + bias  (proven R7 kernel).
// ---------------------------------------------------------------------------
#define GPAD 40

__global__ __launch_bounds__(256) void qkv_mma_kernel() {
    __shared__ __align__(16) __nv_bfloat16 As[2][128][GPAD];
    __shared__ __align__(16) __nv_bfloat16 BsH[2][64][GPAD];
    __shared__ __align__(16) __nv_bfloat16 BsL[2][64][GPAD];

    int tid  = threadIdx.x;
    int warp = tid >> 5;
    int lane = tid & 31;
    int wm   = warp >> 1;
    int wn   = warp & 1;
    int g    = lane >> 2;
    int tig  = lane & 3;
    int m0 = blockIdx.x * 128;
    int w  = blockIdx.y >> 2;
    int o0 = (blockIdx.y & 3) * 64;
    size_t w_off = (size_t)w * 65536 + (size_t)o0 * CDIM;

    float c[2][4][4] = {};

    auto stage = [&](int s, int k0) {
#pragma unroll
        for (int i = 0; i < 2; i++) {
            int idx = tid * 2 + i;
            int row = idx >> 2, c8 = (idx & 3) * 8;
            cp_async16(&As[s][row][c8], g_tok + (size_t)(m0 + row) * CDIM + k0 + c8);
        }
        {
            int row = tid >> 2, c8 = (tid & 3) * 8;
            size_t go = w_off + (size_t)row * CDIM + k0 + c8;
            cp_async16(&BsH[s][row][c8], g_wqkv_hi + go);
            cp_async16(&BsL[s][row][c8], g_wqkv_lo + go);
        }
        cp_commit();
    };

    stage(0, 0);

#pragma unroll
    for (int it = 0; it < 8; it++) {
        int s = it & 1;
        asm volatile("cp.async.wait_group 0;\n");
        __syncthreads();
        if (it < 7) stage(s ^ 1, (it + 1) * 32);

        unsigned af[2][2][4];
        unsigned bfH[4][2][2], bfL[4][2][2];
#pragma unroll
        for (int mt = 0; mt < 2; mt++) {
            int r = wm * 32 + mt * 16 + g;
            const unsigned* h0 = (const unsigned*)&As[s][r][0];
            const unsigned* h1 = (const unsigned*)&As[s][r + 8][0];
#pragma unroll
            for (int kc = 0; kc < 2; kc++) {
                af[mt][kc][0] = h0[kc * 8 + tig];
                af[mt][kc][1] = h1[kc * 8 + tig];
                af[mt][kc][2] = h0[kc * 8 + tig + 4];
                af[mt][kc][3] = h1[kc * 8 + tig + 4];
            }
        }
#pragma unroll
        for (int nt = 0; nt < 4; nt++) {
            int r = wn * 32 + nt * 8 + g;
            const unsigned* rh = (const unsigned*)&BsH[s][r][0];
            const unsigned* rl = (const unsigned*)&BsL[s][r][0];
#pragma unroll
            for (int kc = 0; kc < 2; kc++) {
                bfH[nt][kc][0] = rh[kc * 8 + tig];
                bfH[nt][kc][1] = rh[kc * 8 + tig + 4];
                bfL[nt][kc][0] = rl[kc * 8 + tig];
                bfL[nt][kc][1] = rl[kc * 8 + tig + 4];
            }
        }

#pragma unroll
        for (int mt = 0; mt < 2; mt++)
#pragma unroll
            for (int nt = 0; nt < 4; nt++)
#pragma unroll
                for (int kc = 0; kc < 2; kc++) {
                    mma16816(c[mt][nt], af[mt][kc], bfH[nt][kc]);
                    mma16816(c[mt][nt], af[mt][kc], bfL[nt][kc]);
                }
    }

#pragma unroll
    for (int mt = 0; mt < 2; mt++) {
        int row0 = m0 + wm * 32 + mt * 16 + g;
#pragma unroll
        for (int nt = 0; nt < 4; nt++) {
            int o  = o0 + wn * 32 + nt * 8 + 2 * tig;
            float b0 = g_bias[w * 256 + o];
            float b1 = g_bias[w * 256 + o + 1];
#pragma unroll
            for (int half = 0; half < 2; half++) {
                int row = row0 + half * 8;
                int b = row >> 12;
                int n = row & 4095;
                float v0 = c[mt][nt][2 * half + 0] + b0;
                float v1 = c[mt][nt][2 * half + 1] + b1;
                if (w == 0) {
                    *(unsigned*)&g_q[(((size_t)(b * HEADS + (o >> 5))) * NTOK + n) * DK + (o & 31)] =
                        pack_bf16(v0 * QSCALE, v1 * QSCALE);
                } else if (w == 1) {
                    *(unsigned*)&g_k[(((size_t)(b * HEADS + (o >> 5))) * NTOK + n) * DK + (o & 31)] =
                        pack_bf16(v0, v1);
                } else {
                    __nv_bfloat16* base = g_vt +
                        ((size_t)(b * HEADS + (o >> 5))) * DK * NTOK + n;
                    base[(size_t)(o & 31) * NTOK]       = __float2bfloat16(v0);
                    base[(size_t)((o & 31) + 1) * NTOK] = __float2bfloat16(v1);
                }
            }
        }
    }
}

// ---------------------------------------------------------------------------
// Output projection: split-bf16 (hi/lo both operands) — proven R4 kernel.
// ---------------------------------------------------------------------------
__global__ __launch_bounds__(256) void gemm_o_kernel(const __nv_bfloat16* __restrict__ Ah,
                                                     const __nv_bfloat16* __restrict__ Al,
                                                     const float* __restrict__ W,
                                                     const float* __restrict__ bias,
                                                     float* __restrict__ Cout) {
    __shared__ __nv_bfloat16 AsH[128][GPAD];
    __shared__ __nv_bfloat16 AsL[128][GPAD];
    __shared__ __nv_bfloat16 BsH[64][GPAD];
    __shared__ __nv_bfloat16 BsL[64][GPAD];

    int tid  = threadIdx.x;
    int warp = tid >> 5;
    int lane = tid & 31;
    int wm   = warp >> 1;
    int wn   = warp & 1;
    int g    = lane >> 2;
    int tig  = lane & 3;
    int m0 = blockIdx.x * 128;
    int o0 = blockIdx.y * 64;

    float c[2][4][4] = {};

    uint4  ah_reg[2], al_reg[2];
    float4 w_reg[2];

    auto ldg_stage = [&](int k0) {
#pragma unroll
        for (int i = 0; i < 2; i++) {
            int idx = tid + i * 256;
            size_t aoff = ((size_t)(m0 + (idx >> 2))) * CDIM + k0 + (idx & 3) * 8;
            ah_reg[i] = *(const uint4*)&Ah[aoff];
            al_reg[i] = *(const uint4*)&Al[aoff];
            w_reg[i]  = *(const float4*)&W[((size_t)(o0 + (idx >> 3))) * CDIM + k0 + (idx & 7) * 4];
        }
    };
    auto sts_stage = [&]() {
#pragma unroll
        for (int i = 0; i < 2; i++) {
            int idx = tid + i * 256;
            *(uint4*)&AsH[idx >> 2][(idx & 3) * 8] = ah_reg[i];
            *(uint4*)&AsL[idx >> 2][(idx & 3) * 8] = al_reg[i];
            float w[4] = {w_reg[i].x, w_reg[i].y, w_reg[i].z, w_reg[i].w};
            __nv_bfloat16 wh[4], wl[4];
#pragma unroll
            for (int j = 0; j < 4; j++) split_bf16(w[j], wh[j], wl[j]);
            *(uint2*)&BsH[idx >> 3][(idx & 7) * 4] = *(uint2*)wh;
            *(uint2*)&BsL[idx >> 3][(idx & 7) * 4] = *(uint2*)wl;
        }
    };

    ldg_stage(0);
    sts_stage();
    __syncthreads();

#pragma unroll
    for (int it = 0; it < 8; it++) {
        if (it < 7) ldg_stage((it + 1) * 32);

        unsigned afH[2][2][4], afL[2][2][4];
        unsigned bfH[4][2][2], bfL[4][2][2];
#pragma unroll
        for (int mt = 0; mt < 2; mt++) {
            int r = wm * 32 + mt * 16 + g;
            const unsigned* h0 = (const unsigned*)&AsH[r][0];
            const unsigned* h1 = (const unsigned*)&AsH[r + 8][0];
            const unsigned* l0 = (const unsigned*)&AsL[r][0];
            const unsigned* l1 = (const unsigned*)&AsL[r + 8][0];
#pragma unroll
            for (int kc = 0; kc < 2; kc++) {
                afH[mt][kc][0] = h0[kc * 8 + tig];
                afH[mt][kc][1] = h1[kc * 8 + tig];
                afH[mt][kc][2] = h0[kc * 8 + tig + 4];
                afH[mt][kc][3] = h1[kc * 8 + tig + 4];
                afL[mt][kc][0] = l0[kc * 8 + tig];
                afL[mt][kc][1] = l1[kc * 8 + tig];
                afL[mt][kc][2] = l0[kc * 8 + tig + 4];
                afL[mt][kc][3] = l1[kc * 8 + tig + 4];
            }
        }
#pragma unroll
        for (int nt = 0; nt < 4; nt++) {
            int r = wn * 32 + nt * 8 + g;
            const unsigned* rh = (const unsigned*)&BsH[r][0];
            const unsigned* rl = (const unsigned*)&BsL[r][0];
#pragma unroll
            for (int kc = 0; kc < 2; kc++) {
                bfH[nt][kc][0] = rh[kc * 8 + tig];
                bfH[nt][kc][1] = rh[kc * 8 + tig + 4];
                bfL[nt][kc][0] = rl[kc * 8 + tig];
                bfL[nt][kc][1] = rl[kc * 8 + tig + 4];
            }
        }

#pragma unroll
        for (int mt = 0; mt < 2; mt++)
#pragma unroll
            for (int nt = 0; nt < 4; nt++)
#pragma unroll
                for (int kc = 0; kc < 2; kc++) {
                    mma16816(c[mt][nt], afH[mt][kc], bfH[nt][kc]);
                    mma16816(c[mt][nt], afH[mt][kc], bfL[nt][kc]);
                    mma16816(c[mt][nt], afL[mt][kc], bfH[nt][kc]);
                }

        __syncthreads();
        if (it < 7) {
            sts_stage();
            __syncthreads();
        }
    }

#pragma unroll
    for (int mt = 0; mt < 2; mt++) {
        int row0 = m0 + wm * 32 + mt * 16 + g;
#pragma unroll
        for (int nt = 0; nt < 4; nt++) {
            int o  = o0 + wn * 32 + nt * 8 + 2 * tig;
            float b0 = __ldg(&bias[o]);
            float b1 = __ldg(&bias[o + 1]);
#pragma unroll
            for (int half = 0; half < 2; half++) {
                int row = row0 + half * 8;
                int b = row >> 12;
                int n = row & 4095;
                float* base = Cout + (size_t)b * CDIM * NTOK + n;
                base[(size_t)o * NTOK]       = c[mt][nt][2 * half + 0] + b0;
                base[(size_t)(o + 1) * NTOK] = c[mt][nt][2 * half + 1] + b1;
            }
        }
    }
}

// ---------------------------------------------------------------------------
// Flash attention (R7 shape + ldmatrix fragment loads):
// 256 thr / 8 warps, 16 q-rows per warp, BR=128, BC=64, cp.async S=2,
// one __syncthreads per tile, no online max, bf16x2 exp2, l via ones-MMA.
// K-frags: 1 ldmatrix.x4 per t (8/tile). V-frags: 2 per dt (8/tile).
// ---------------------------------------------------------------------------
#define BR 128
#define BC 64
#define KPAD 40
#define VPAD 72
#define ONES_BF16X2 0x3F803F80u

__global__ __launch_bounds__(256) void flash_mma_kernel() {
    __shared__ __align__(16) __nv_bfloat16 Ks[2][BC][KPAD];
    __shared__ __align__(16) __nv_bfloat16 Vs[2][DK][VPAD];

    int bh    = blockIdx.y;
    int qbase = blockIdx.x * BR;
    int tid   = threadIdx.x;
    int warp  = tid >> 5;
    int lane  = tid & 31;
    int g     = lane >> 2;
    int tig   = lane & 3;

    const __nv_bfloat16* qb = g_q  + (size_t)bh * NTOK * DK;
    const __nv_bfloat16* kb = g_k  + (size_t)bh * NTOK * DK;
    const __nv_bfloat16* vb = g_vt + (size_t)bh * DK * NTOK;

    int kr = tid >> 2, kq = tid & 3;
    int vd = tid >> 3, vq = tid & 7;

    auto stage_load = [&](int s, int n0) {
        cp_async16(&Ks[s][kr][kq * 8], kb + (size_t)(n0 + kr) * DK + kq * 8);
        cp_async16(&Vs[s][vd][vq * 8], vb + (size_t)vd * NTOK + n0 + vq * 8);
        cp_commit();
    };

    // ldmatrix addressing: lane provides row (lane&7) of matrix (lane>>3)
    int lmr = lane & 7, lmc = lane >> 3;
    unsigned ks_smem = (unsigned)__cvta_generic_to_shared(&Ks[0][0][0])
                     + (unsigned)(lmr * (KPAD * 2) + lmc * 16);
    unsigned vs_smem = (unsigned)__cvta_generic_to_shared(&Vs[0][0][0])
                     + (unsigned)(lmr * (VPAD * 2) + lmc * 16);

    unsigned qf[2][4];
    {
        int r0 = qbase + warp * 16 + g;
        const unsigned* q0 = (const unsigned*)(qb + (size_t)r0 * DK);
        const unsigned* q1 = (const unsigned*)(qb + (size_t)(r0 + 8) * DK);
#pragma unroll
        for (int cc = 0; cc < 2; cc++) {
            qf[cc][0] = q0[8 * cc + tig];
            qf[cc][1] = q1[8 * cc + tig];
            qf[cc][2] = q0[8 * cc + tig + 4];
            qf[cc][3] = q1[8 * cc + tig + 4];
        }
    }

    float O[4][4] = {};
    float lacc[4] = {};
    const unsigned onesb[2] = {ONES_BF16X2, ONES_BF16X2};

    stage_load(0, 0);

    const int NT = NTOK / BC;
    for (int it = 0; it < NT; it++) {
        int s = it & 1;
        asm volatile("cp.async.wait_group 0;\n");
        __syncthreads();
        if (it + 1 < NT) stage_load(s ^ 1, (it + 1) * BC);

        unsigned ksb = ks_smem + (unsigned)(s * BC * KPAD * 2);
        unsigned vsb = vs_smem + (unsigned)(s * DK * VPAD * 2);

        // S = Q@K^T: one ldmatrix.x4 per t gives both kc chunks
        float S[8][4];
#pragma unroll
        for (int t = 0; t < 8; t++) {
            unsigned kf[4];
            ldsm4(kf, ksb + (unsigned)(t * 8 * KPAD * 2));
            S[t][0] = S[t][1] = S[t][2] = S[t][3] = 0.0f;
            mma16816(S[t], qf[0], &kf[0]);
            mma16816(S[t], qf[1], &kf[2]);
        }

        unsigned Pf[4][4];
#pragma unroll
        for (int kc = 0; kc < 4; kc++) {
            Pf[kc][0] = ex2_bf16x2(pack_bf16(S[2 * kc][0],     S[2 * kc][1]));
            Pf[kc][1] = ex2_bf16x2(pack_bf16(S[2 * kc][2],     S[2 * kc][3]));
            Pf[kc][2] = ex2_bf16x2(pack_bf16(S[2 * kc + 1][0], S[2 * kc + 1][1]));
            Pf[kc][3] = ex2_bf16x2(pack_bf16(S[2 * kc + 1][2], S[2 * kc + 1][3]));
        }

        // O += P @ V: two ldmatrix.x4 per dt give all 4 kc chunks
#pragma unroll
        for (int dt = 0; dt < 4; dt++) {
            unsigned vf[8];
            unsigned va = vsb + (unsigned)(dt * 8 * VPAD * 2);
            ldsm4(&vf[0], va);
            ldsm4(&vf[4], va + 64);
            mma16816(O[dt], Pf[0], &vf[0]);
            mma16816(O[dt], Pf[1], &vf[2]);
            mma16816(O[dt], Pf[2], &vf[4]);
            mma16816(O[dt], Pf[3], &vf[6]);
        }
#pragma unroll
        for (int kc = 0; kc < 4; kc++)
            mma16816(lacc, Pf[kc], onesb);
    }

    float inv0 = 1.0f / lacc[0];
    float inv1 = 1.0f / lacc[2];

    int b = bh >> 3, h = bh & 7;
    int row0 = qbase + warp * 16 + g;
    size_t o0off = ((size_t)(b * NTOK + row0) * CDIM) + h * DK;
    size_t o1off = ((size_t)(b * NTOK + row0 + 8) * CDIM) + h * DK;
#pragma unroll
    for (int dt = 0; dt < 4; dt++) {
        int d = 8 * dt + 2 * tig;
        float a0 = O[dt][0] * inv0, a1 = O[dt][1] * inv0;
        float b0 = O[dt][2] * inv1, b1 = O[dt][3] * inv1;
        __nv_bfloat16 h0, l0b, h1, l1b;
        split_bf16(a0, h0, l0b); split_bf16(a1, h1, l1b);
        *(unsigned*)&g_att_hi[o0off + d] = pack_bf16(__bfloat162float(h0), __bfloat162float(h1));
        *(unsigned*)&g_att_lo[o0off + d] = pack_bf16(__bfloat162float(l0b), __bfloat162float(l1b));
        split_bf16(b0, h0, l0b); split_bf16(b1, h1, l1b);
        *(unsigned*)&g_att_hi[o1off + d] = pack_bf16(__bfloat162float(h0), __bfloat162float(h1));
        *(unsigned*)&g_att_lo[o1off + d] = pack_bf16(__bfloat162float(l0b), __bfloat162float(l1b));
    }
}

// ---------------------------------------------------------------------------
extern "C" void kernel_launch(void* const* d_in, const int* in_sizes, int n_in,
                              void* d_out, int out_size) {
    const float* x  = (const float*)d_in[0];
    const float* Wq = (const float*)d_in[1];
    const float* bq = (const float*)d_in[2];
    const float* Wk = (const float*)d_in[3];
    const float* bk = (const float*)d_in[4];
    const float* Wv = (const float*)d_in[5];
    const float* bv = (const float*)d_in[6];
    const float* Wo = (const float*)d_in[7];
    const float* bo = (const float*)d_in[8];
    float* out = (float*)d_out;

    static void *p_att_hi = nullptr, *p_att_lo = nullptr;
    if (!p_att_hi) {
        cudaGetSymbolAddress(&p_att_hi, g_att_hi);
        cudaGetSymbolAddress(&p_att_lo, g_att_lo);
    }

    pe_tok_kernel<<<1024, 256>>>(x);
    split_w_kernel<<<192, 256>>>(Wq, Wk, Wv, bq, bk, bv);

    qkv_mma_kernel<<<dim3(MROWS / 128, 12), 256>>>();

    flash_mma_kernel<<<dim3(NTOK / BR, BATCH * HEADS), 256>>>();

    gemm_o_kernel<<<dim3(MROWS / 128, CDIM / 64), 256>>>(
        (const __nv_bfloat16*)p_att_hi, (const __nv_bfloat16*)p_att_lo, Wo, bo, out);
}

// round 13
// speedup vs baseline: 1.5443x; 1.0018x over previous
#include <cuda_runtime.h>
#include <cuda_bf16.h>
#include <math.h>

#define HEADS 8
#define CDIM  256
#define NTOK  4096
#define BATCH 2
#define DK    32
#define MROWS (BATCH * NTOK)   // 8192

#define QSCALE 0.25500526114838825f

// Scratch (no allocations allowed)
__device__ __nv_bfloat16 g_tok[BATCH * NTOK * CDIM];
__device__ __nv_bfloat16 g_wqkv_hi[3 * CDIM * CDIM];
__device__ __nv_bfloat16 g_wqkv_lo[3 * CDIM * CDIM];
__device__ __nv_bfloat16 g_wo_hi[CDIM * CDIM];
__device__ __nv_bfloat16 g_wo_lo[CDIM * CDIM];
__device__ float         g_bias[4 * CDIM];                 // bq|bk|bv|bo
__device__ __nv_bfloat16 g_q[BATCH * HEADS * NTOK * DK];
__device__ __nv_bfloat16 g_k[BATCH * HEADS * NTOK * DK];
__device__ __nv_bfloat16 g_vt[BATCH * HEADS * DK * NTOK];
__device__ __nv_bfloat16 g_att_hi[BATCH * NTOK * CDIM];
__device__ __nv_bfloat16 g_att_lo[BATCH * NTOK * CDIM];

__device__ __forceinline__ unsigned pack_bf16(float a, float b) {
    __nv_bfloat162 t = __float22bfloat162_rn(make_float2(a, b));
    return *(unsigned*)&t;
}
__device__ __forceinline__ void split_bf16(float v, __nv_bfloat16& hi, __nv_bfloat16& lo) {
    hi = __float2bfloat16(v);
    lo = __float2bfloat16(v - __bfloat162float(hi));
}
__device__ __forceinline__ unsigned ex2_bf16x2(unsigned s) {
    unsigned r;
    asm volatile("ex2.approx.ftz.bf16x2 %0, %1;\n" : "=r"(r) : "r"(s));
    return r;
}
__device__ __forceinline__ void cp_async16(void* smem_dst, const void* gsrc) {
    unsigned saddr = (unsigned)__cvta_generic_to_shared(smem_dst);
    asm volatile("cp.async.ca.shared.global [%0], [%1], 16;\n" :: "r"(saddr), "l"(gsrc));
}
__device__ __forceinline__ void cp_commit() {
    asm volatile("cp.async.commit_group;\n");
}
__device__ __forceinline__ void mma16816(float c[4], const unsigned a[4], const unsigned b[2]) {
    asm volatile(
        "mma.sync.aligned.m16n8k16.row.col.f32.bf16.bf16.f32 "
        "{%0,%1,%2,%3}, {%4,%5,%6,%7}, {%8,%9}, {%0,%1,%2,%3};\n"
        : "+f"(c[0]), "+f"(c[1]), "+f"(c[2]), "+f"(c[3])
        : "r"(a[0]), "r"(a[1]), "r"(a[2]), "r"(a[3]), "r"(b[0]), "r"(b[1]));
}
__device__ __forceinline__ void ldsm4(unsigned r[4], unsigned saddr) {
    asm volatile("ldmatrix.sync.aligned.m8n8.x4.shared.b16 {%0,%1,%2,%3}, [%4];\n"
                 : "=r"(r[0]), "=r"(r[1]), "=r"(r[2]), "=r"(r[3]) : "r"(saddr));
}

// ---------------------------------------------------------------------------
// Kernel 1: tok = x + PE (bf16). Coalesced both sides.
// ---------------------------------------------------------------------------
__global__ __launch_bounds__(256) void pe_tok_kernel(const float* __restrict__ x) {
    int n_lo   = threadIdx.x & 31;
    int oct_lo = threadIdx.x >> 5;
    int n_hi   = blockIdx.x & 127;
    int oct_hi = (blockIdx.x >> 7) & 3;
    int b = blockIdx.x >> 9;

    int n = n_hi * 32 + n_lo;
    int ch0 = (oct_hi * 8 + oct_lo) * 8;
    int yy = n >> 6;
    int xx = n & 63;

    __nv_bfloat16 vh[8];
#pragma unroll
    for (int j = 0; j < 8; j++) {
        int ch = ch0 + j;
        int i, pos;
        if (ch < 128) { i = ch >> 1;         pos = xx; }
        else          { i = (ch - 128) >> 1; pos = yy; }
        float div = __expf(-(float)(2 * i) * (9.210340371976184f / 128.0f));
        float arg = (float)pos * div;
        float pe  = (ch & 1) ? cosf(arg) : sinf(arg);
        vh[j] = __float2bfloat16(x[((size_t)(b * CDIM + ch)) * NTOK + n] + pe);
    }
    *(uint4*)&g_tok[((size_t)(b * NTOK) + n) * CDIM + ch0] = *(uint4*)vh;
}

// ---------------------------------------------------------------------------
// Kernel 2: split Wq/Wk/Wv/Wo into bf16 hi/lo and gather all biases.
// grid 256 x 256 threads: t = 0..65535, 4 floats each.
// ---------------------------------------------------------------------------
__global__ __launch_bounds__(256) void split_w_kernel(const float* __restrict__ Wq,
                                                      const float* __restrict__ Wk,
                                                      const float* __restrict__ Wv,
                                                      const float* __restrict__ Wo,
                                                      const float* __restrict__ bq,
                                                      const float* __restrict__ bk,
                                                      const float* __restrict__ bv,
                                                      const float* __restrict__ bo) {
    int t = blockIdx.x * 256 + threadIdx.x;      // 0..65535
    int idx4 = t * 4;
    int w = idx4 >> 16;                          // 0..3
    const float* src = (w == 0) ? Wq : (w == 1) ? Wk : (w == 2) ? Wv : Wo;
    float4 v = *(const float4*)&src[idx4 & 65535];
    __nv_bfloat16 h[4], l[4];
    split_bf16(v.x, h[0], l[0]); split_bf16(v.y, h[1], l[1]);
    split_bf16(v.z, h[2], l[2]); split_bf16(v.w, h[3], l[3]);
    if (w < 3) {
        *(uint2*)&g_wqkv_hi[idx4] = *(uint2*)h;
        *(uint2*)&g_wqkv_lo[idx4] = *(uint2*)l;
    } else {
        *(uint2*)&g_wo_hi[idx4 & 65535] = *(uint2*)h;
        *(uint2*)&g_wo_lo[idx4 & 65535] = *(uint2*)l;
    }
    if (t < 1024) {
        int which = t >> 8;
        const float* bsrc = (which == 0) ? bq : (which == 1) ? bk : (which == 2) ? bv : bo;
        g_bias[t] = bsrc[t & 255];
    }
}

// ---------------------------------------------------------------------------
// Fused QKV GEMM: C = tok(bf16) @ (Wh + Wl)^T + bias  (proven R7 kernel).
// ---------------------------------------------------------------------------
#define GPAD 40

__global__ __launch_bounds__(256) void qkv_mma_kernel() {
    __shared__ __align__(16) __nv_bfloat16 As[2][128][GPAD];
    __shared__ __align__(16) __nv_bfloat16 BsH[2][64][GPAD];
    __shared__ __align__(16) __nv_bfloat16 BsL[2][64][GPAD];

    int tid  = threadIdx.x;
    int warp = tid >> 5;
    int lane = tid & 31;
    int wm   = warp >> 1;
    int wn   = warp & 1;
    int g    = lane >> 2;
    int tig  = lane & 3;
    int m0 = blockIdx.x * 128;
    int w  = blockIdx.y >> 2;
    int o0 = (blockIdx.y & 3) * 64;
    size_t w_off = (size_t)w * 65536 + (size_t)o0 * CDIM;

    float c[2][4][4] = {};

    auto stage = [&](int s, int k0) {
#pragma unroll
        for (int i = 0; i < 2; i++) {
            int idx = tid * 2 + i;
            int row = idx >> 2, c8 = (idx & 3) * 8;
            cp_async16(&As[s][row][c8], g_tok + (size_t)(m0 + row) * CDIM + k0 + c8);
        }
        {
            int row = tid >> 2, c8 = (tid & 3) * 8;
            size_t go = w_off + (size_t)row * CDIM + k0 + c8;
            cp_async16(&BsH[s][row][c8], g_wqkv_hi + go);
            cp_async16(&BsL[s][row][c8], g_wqkv_lo + go);
        }
        cp_commit();
    };

    stage(0, 0);

#pragma unroll
    for (int it = 0; it < 8; it++) {
        int s = it & 1;
        asm volatile("cp.async.wait_group 0;\n");
        __syncthreads();
        if (it < 7) stage(s ^ 1, (it + 1) * 32);

        unsigned af[2][2][4];
        unsigned bfH[4][2][2], bfL[4][2][2];
#pragma unroll
        for (int mt = 0; mt < 2; mt++) {
            int r = wm * 32 + mt * 16 + g;
            const unsigned* h0 = (const unsigned*)&As[s][r][0];
            const unsigned* h1 = (const unsigned*)&As[s][r + 8][0];
#pragma unroll
            for (int kc = 0; kc < 2; kc++) {
                af[mt][kc][0] = h0[kc * 8 + tig];
                af[mt][kc][1] = h1[kc * 8 + tig];
                af[mt][kc][2] = h0[kc * 8 + tig + 4];
                af[mt][kc][3] = h1[kc * 8 + tig + 4];
            }
        }
#pragma unroll
        for (int nt = 0; nt < 4; nt++) {
            int r = wn * 32 + nt * 8 + g;
            const unsigned* rh = (const unsigned*)&BsH[s][r][0];
            const unsigned* rl = (const unsigned*)&BsL[s][r][0];
#pragma unroll
            for (int kc = 0; kc < 2; kc++) {
                bfH[nt][kc][0] = rh[kc * 8 + tig];
                bfH[nt][kc][1] = rh[kc * 8 + tig + 4];
                bfL[nt][kc][0] = rl[kc * 8 + tig];
                bfL[nt][kc][1] = rl[kc * 8 + tig + 4];
            }
        }

#pragma unroll
        for (int mt = 0; mt < 2; mt++)
#pragma unroll
            for (int nt = 0; nt < 4; nt++)
#pragma unroll
                for (int kc = 0; kc < 2; kc++) {
                    mma16816(c[mt][nt], af[mt][kc], bfH[nt][kc]);
                    mma16816(c[mt][nt], af[mt][kc], bfL[nt][kc]);
                }
    }

#pragma unroll
    for (int mt = 0; mt < 2; mt++) {
        int row0 = m0 + wm * 32 + mt * 16 + g;
#pragma unroll
        for (int nt = 0; nt < 4; nt++) {
            int o  = o0 + wn * 32 + nt * 8 + 2 * tig;
            float b0 = g_bias[w * 256 + o];
            float b1 = g_bias[w * 256 + o + 1];
#pragma unroll
            for (int half = 0; half < 2; half++) {
                int row = row0 + half * 8;
                int b = row >> 12;
                int n = row & 4095;
                float v0 = c[mt][nt][2 * half + 0] + b0;
                float v1 = c[mt][nt][2 * half + 1] + b1;
                if (w == 0) {
                    *(unsigned*)&g_q[(((size_t)(b * HEADS + (o >> 5))) * NTOK + n) * DK + (o & 31)] =
                        pack_bf16(v0 * QSCALE, v1 * QSCALE);
                } else if (w == 1) {
                    *(unsigned*)&g_k[(((size_t)(b * HEADS + (o >> 5))) * NTOK + n) * DK + (o & 31)] =
                        pack_bf16(v0, v1);
                } else {
                    __nv_bfloat16* base = g_vt +
                        ((size_t)(b * HEADS + (o >> 5))) * DK * NTOK + n;
                    base[(size_t)(o & 31) * NTOK]       = __float2bfloat16(v0);
                    base[(size_t)((o & 31) + 1) * NTOK] = __float2bfloat16(v1);
                }
            }
        }
    }
}

// ---------------------------------------------------------------------------
// Output projection: 3-term split-bf16 (AhBh + AhBl + AlBh), cp.async S=2,
// pre-split Wo, one __syncthreads per K-step.
// ---------------------------------------------------------------------------
__global__ __launch_bounds__(256) void gemm_o_kernel(float* __restrict__ Cout) {
    __shared__ __align__(16) __nv_bfloat16 AsH[2][128][GPAD];
    __shared__ __align__(16) __nv_bfloat16 AsL[2][128][GPAD];
    __shared__ __align__(16) __nv_bfloat16 BsH[2][64][GPAD];
    __shared__ __align__(16) __nv_bfloat16 BsL[2][64][GPAD];

    int tid  = threadIdx.x;
    int warp = tid >> 5;
    int lane = tid & 31;
    int wm   = warp >> 1;
    int wn   = warp & 1;
    int g    = lane >> 2;
    int tig  = lane & 3;
    int m0 = blockIdx.x * 128;
    int o0 = blockIdx.y * 64;

    float c[2][4][4] = {};

    auto stage = [&](int s, int k0) {
#pragma unroll
        for (int i = 0; i < 2; i++) {
            int idx = tid * 2 + i;
            int row = idx >> 2, c8 = (idx & 3) * 8;
            size_t ao = (size_t)(m0 + row) * CDIM + k0 + c8;
            cp_async16(&AsH[s][row][c8], g_att_hi + ao);
            cp_async16(&AsL[s][row][c8], g_att_lo + ao);
        }
        {
            int row = tid >> 2, c8 = (tid & 3) * 8;
            size_t go = (size_t)(o0 + row) * CDIM + k0 + c8;
            cp_async16(&BsH[s][row][c8], g_wo_hi + go);
            cp_async16(&BsL[s][row][c8], g_wo_lo + go);
        }
        cp_commit();
    };

    stage(0, 0);

#pragma unroll
    for (int it = 0; it < 8; it++) {
        int s = it & 1;
        asm volatile("cp.async.wait_group 0;\n");
        __syncthreads();
        if (it < 7) stage(s ^ 1, (it + 1) * 32);

        unsigned afH[2][2][4], afL[2][2][4];
        unsigned bfH[4][2][2], bfL[4][2][2];
#pragma unroll
        for (int mt = 0; mt < 2; mt++) {
            int r = wm * 32 + mt * 16 + g;
            const unsigned* h0 = (const unsigned*)&AsH[s][r][0];
            const unsigned* h1 = (const unsigned*)&AsH[s][r + 8][0];
            const unsigned* l0 = (const unsigned*)&AsL[s][r][0];
            const unsigned* l1 = (const unsigned*)&AsL[s][r + 8][0];
#pragma unroll
            for (int kc = 0; kc < 2; kc++) {
                afH[mt][kc][0] = h0[kc * 8 + tig];
                afH[mt][kc][1] = h1[kc * 8 + tig];
                afH[mt][kc][2] = h0[kc * 8 + tig + 4];
                afH[mt][kc][3] = h1[kc * 8 + tig + 4];
                afL[mt][kc][0] = l0[kc * 8 + tig];
                afL[mt][kc][1] = l1[kc * 8 + tig];
                afL[mt][kc][2] = l0[kc * 8 + tig + 4];
                afL[mt][kc][3] = l1[kc * 8 + tig + 4];
            }
        }
#pragma unroll
        for (int nt = 0; nt < 4; nt++) {
            int r = wn * 32 + nt * 8 + g;
            const unsigned* rh = (const unsigned*)&BsH[s][r][0];
            const unsigned* rl = (const unsigned*)&BsL[s][r][0];
#pragma unroll
            for (int kc = 0; kc < 2; kc++) {
                bfH[nt][kc][0] = rh[kc * 8 + tig];
                bfH[nt][kc][1] = rh[kc * 8 + tig + 4];
                bfL[nt][kc][0] = rl[kc * 8 + tig];
                bfL[nt][kc][1] = rl[kc * 8 + tig + 4];
            }
        }

#pragma unroll
        for (int mt = 0; mt < 2; mt++)
#pragma unroll
            for (int nt = 0; nt < 4; nt++)
#pragma unroll
                for (int kc = 0; kc < 2; kc++) {
                    mma16816(c[mt][nt], afH[mt][kc], bfH[nt][kc]);
                    mma16816(c[mt][nt], afH[mt][kc], bfL[nt][kc]);
                    mma16816(c[mt][nt], afL[mt][kc], bfH[nt][kc]);
                }
    }

#pragma unroll
    for (int mt = 0; mt < 2; mt++) {
        int row0 = m0 + wm * 32 + mt * 16 + g;
#pragma unroll
        for (int nt = 0; nt < 4; nt++) {
            int o  = o0 + wn * 32 + nt * 8 + 2 * tig;
            float b0 = g_bias[768 + o];
            float b1 = g_bias[768 + o + 1];
#pragma unroll
            for (int half = 0; half < 2; half++) {
                int row = row0 + half * 8;
                int b = row >> 12;
                int n = row & 4095;
                float* base = Cout + (size_t)b * CDIM * NTOK + n;
                base[(size_t)o * NTOK]       = c[mt][nt][2 * half + 0] + b0;
                base[(size_t)(o + 1) * NTOK] = c[mt][nt][2 * half + 1] + b1;
            }
        }
    }
}

// ---------------------------------------------------------------------------
// Flash attention: 256 thr / 8 warps, 16 q-rows per warp, BR=128, BC=64,
// cp.async S=2, one sync per tile, ldmatrix frags, exp2 fused into t-loop
// (S live range 4 regs), forced 4 blocks/SM for occupancy.
// ---------------------------------------------------------------------------
#define BR 128
#define BC 64
#define KPAD 40
#define VPAD 72
#define ONES_BF16X2 0x3F803F80u

__global__ __launch_bounds__(256, 4) void flash_mma_kernel() {
    __shared__ __align__(16) __nv_bfloat16 Ks[2][BC][KPAD];
    __shared__ __align__(16) __nv_bfloat16 Vs[2][DK][VPAD];

    int bh    = blockIdx.y;
    int qbase = blockIdx.x * BR;
    int tid   = threadIdx.x;
    int warp  = tid >> 5;
    int lane  = tid & 31;
    int g     = lane >> 2;
    int tig   = lane & 3;

    const __nv_bfloat16* qb = g_q  + (size_t)bh * NTOK * DK;
    const __nv_bfloat16* kb = g_k  + (size_t)bh * NTOK * DK;
    const __nv_bfloat16* vb = g_vt + (size_t)bh * DK * NTOK;

    int kr = tid >> 2, kq = tid & 3;
    int vd = tid >> 3, vq = tid & 7;

    auto stage_load = [&](int s, int n0) {
        cp_async16(&Ks[s][kr][kq * 8], kb + (size_t)(n0 + kr) * DK + kq * 8);
        cp_async16(&Vs[s][vd][vq * 8], vb + (size_t)vd * NTOK + n0 + vq * 8);
        cp_commit();
    };

    int lmr = lane & 7, lmc = lane >> 3;
    unsigned ks_smem = (unsigned)__cvta_generic_to_shared(&Ks[0][0][0])
                     + (unsigned)(lmr * (KPAD * 2) + lmc * 16);
    unsigned vs_smem = (unsigned)__cvta_generic_to_shared(&Vs[0][0][0])
                     + (unsigned)(lmr * (VPAD * 2) + lmc * 16);

    unsigned qf[2][4];
    {
        int r0 = qbase + warp * 16 + g;
        const unsigned* q0 = (const unsigned*)(qb + (size_t)r0 * DK);
        const unsigned* q1 = (const unsigned*)(qb + (size_t)(r0 + 8) * DK);
#pragma unroll
        for (int cc = 0; cc < 2; cc++) {
            qf[cc][0] = q0[8 * cc + tig];
            qf[cc][1] = q1[8 * cc + tig];
            qf[cc][2] = q0[8 * cc + tig + 4];
            qf[cc][3] = q1[8 * cc + tig + 4];
        }
    }

    float O[4][4] = {};
    float lacc[4] = {};
    const unsigned onesb[2] = {ONES_BF16X2, ONES_BF16X2};

    stage_load(0, 0);

    const int NT = NTOK / BC;
    for (int it = 0; it < NT; it++) {
        int s = it & 1;
        asm volatile("cp.async.wait_group 0;\n");
        __syncthreads();
        if (it + 1 < NT) stage_load(s ^ 1, (it + 1) * BC);

        unsigned ksb = ks_smem + (unsigned)(s * BC * KPAD * 2);
        unsigned vsb = vs_smem + (unsigned)(s * DK * VPAD * 2);

        // S = Q@K^T with exp2 fused per t (short S live range)
        unsigned Pf[4][4];
#pragma unroll
        for (int t = 0; t < 8; t++) {
            unsigned kf[4];
            ldsm4(kf, ksb + (unsigned)(t * 8 * KPAD * 2));
            float S4[4] = {0.0f, 0.0f, 0.0f, 0.0f};
            mma16816(S4, qf[0], &kf[0]);
            mma16816(S4, qf[1], &kf[2]);
            Pf[t >> 1][(t & 1) * 2 + 0] = ex2_bf16x2(pack_bf16(S4[0], S4[1]));
            Pf[t >> 1][(t & 1) * 2 + 1] = ex2_bf16x2(pack_bf16(S4[2], S4[3]));
        }

        // O += P @ V: two ldmatrix.x4 per dt give all 4 kc chunks
#pragma unroll
        for (int dt = 0; dt < 4; dt++) {
            unsigned vf[8];
            unsigned va = vsb + (unsigned)(dt * 8 * VPAD * 2);
            ldsm4(&vf[0], va);
            ldsm4(&vf[4], va + 64);
            mma16816(O[dt], Pf[0], &vf[0]);
            mma16816(O[dt], Pf[1], &vf[2]);
            mma16816(O[dt], Pf[2], &vf[4]);
            mma16816(O[dt], Pf[3], &vf[6]);
        }
#pragma unroll
        for (int kc = 0; kc < 4; kc++)
            mma16816(lacc, Pf[kc], onesb);
    }

    float inv0 = 1.0f / lacc[0];
    float inv1 = 1.0f / lacc[2];

    int b = bh >> 3, h = bh & 7;
    int row0 = qbase + warp * 16 + g;
    size_t o0off = ((size_t)(b * NTOK + row0) * CDIM) + h * DK;
    size_t o1off = ((size_t)(b * NTOK + row0 + 8) * CDIM) + h * DK;
#pragma unroll
    for (int dt = 0; dt < 4; dt++) {
        int d = 8 * dt + 2 * tig;
        float a0 = O[dt][0] * inv0, a1 = O[dt][1] * inv0;
        float b0 = O[dt][2] * inv1, b1 = O[dt][3] * inv1;
        __nv_bfloat16 h0, l0b, h1, l1b;
        split_bf16(a0, h0, l0b); split_bf16(a1, h1, l1b);
        *(unsigned*)&g_att_hi[o0off + d] = pack_bf16(__bfloat162float(h0), __bfloat162float(h1));
        *(unsigned*)&g_att_lo[o0off + d] = pack_bf16(__bfloat162float(l0b), __bfloat162float(l1b));
        split_bf16(b0, h0, l0b); split_bf16(b1, h1, l1b);
        *(unsigned*)&g_att_hi[o1off + d] = pack_bf16(__bfloat162float(h0), __bfloat162float(h1));
        *(unsigned*)&g_att_lo[o1off + d] = pack_bf16(__bfloat162float(l0b), __bfloat162float(l1b));
    }
}

// ---------------------------------------------------------------------------
extern "C" void kernel_launch(void* const* d_in, const int* in_sizes, int n_in,
                              void* d_out, int out_size) {
    const float* x  = (const float*)d_in[0];
    const float* Wq = (const float*)d_in[1];
    const float* bq = (const float*)d_in[2];
    const float* Wk = (const float*)d_in[3];
    const float* bk = (const float*)d_in[4];
    const float* Wv = (const float*)d_in[5];
    const float* bv = (const float*)d_in[6];
    const float* Wo = (const float*)d_in[7];
    const float* bo = (const float*)d_in[8];
    float* out = (float*)d_out;

    pe_tok_kernel<<<1024, 256>>>(x);
    split_w_kernel<<<256, 256>>>(Wq, Wk, Wv, Wo, bq, bk, bv, bo);

    qkv_mma_kernel<<<dim3(MROWS / 128, 12), 256>>>();

    flash_mma_kernel<<<dim3(NTOK / BR, BATCH * HEADS), 256>>>();

    gemm_o_kernel<<<dim3(MROWS / 128, CDIM / 64), 256>>>(out);
}

// round 14
// speedup vs baseline: 1.6896x; 1.0941x over previous
#include <cuda_runtime.h>
#include <cuda_bf16.h>
#include <math.h>

#define HEADS 8
#define CDIM  256
#define NTOK  4096
#define BATCH 2
#define DK    32
#define MROWS (BATCH * NTOK)   // 8192

#define QSCALE 0.25500526114838825f

// Scratch (no allocations allowed)
__device__ __nv_bfloat16 g_tok[BATCH * NTOK * CDIM];
__device__ __nv_bfloat16 g_wqkv_hi[3 * CDIM * CDIM];
__device__ __nv_bfloat16 g_wqkv_lo[3 * CDIM * CDIM];
__device__ __nv_bfloat16 g_wo_hi[CDIM * CDIM];
__device__ __nv_bfloat16 g_wo_lo[CDIM * CDIM];
__device__ float         g_bias[4 * CDIM];                 // bq|bk|bv|bo
__device__ __nv_bfloat16 g_q[BATCH * HEADS * NTOK * DK];
__device__ __nv_bfloat16 g_k[BATCH * HEADS * NTOK * DK];
__device__ __nv_bfloat16 g_vt[BATCH * HEADS * DK * NTOK];
__device__ __nv_bfloat16 g_att_hi[BATCH * NTOK * CDIM];
__device__ __nv_bfloat16 g_att_lo[BATCH * NTOK * CDIM];

__device__ __forceinline__ unsigned pack_bf16(float a, float b) {
    __nv_bfloat162 t = __float22bfloat162_rn(make_float2(a, b));
    return *(unsigned*)&t;
}
__device__ __forceinline__ void split_bf16(float v, __nv_bfloat16& hi, __nv_bfloat16& lo) {
    hi = __float2bfloat16(v);
    lo = __float2bfloat16(v - __bfloat162float(hi));
}
__device__ __forceinline__ unsigned ex2_bf16x2(unsigned s) {
    unsigned r;
    asm volatile("ex2.approx.ftz.bf16x2 %0, %1;\n" : "=r"(r) : "r"(s));
    return r;
}
__device__ __forceinline__ void cp_async16(void* smem_dst, const void* gsrc) {
    unsigned saddr = (unsigned)__cvta_generic_to_shared(smem_dst);
    asm volatile("cp.async.ca.shared.global [%0], [%1], 16;\n" :: "r"(saddr), "l"(gsrc));
}
__device__ __forceinline__ void cp_commit() {
    asm volatile("cp.async.commit_group;\n");
}
__device__ __forceinline__ void mma16816(float c[4], const unsigned a[4], const unsigned b[2]) {
    asm volatile(
        "mma.sync.aligned.m16n8k16.row.col.f32.bf16.bf16.f32 "
        "{%0,%1,%2,%3}, {%4,%5,%6,%7}, {%8,%9}, {%0,%1,%2,%3};\n"
        : "+f"(c[0]), "+f"(c[1]), "+f"(c[2]), "+f"(c[3])
        : "r"(a[0]), "r"(a[1]), "r"(a[2]), "r"(a[3]), "r"(b[0]), "r"(b[1]));
}
__device__ __forceinline__ void ldsm4(unsigned r[4], unsigned saddr) {
    asm volatile("ldmatrix.sync.aligned.m8n8.x4.shared.b16 {%0,%1,%2,%3}, [%4];\n"
                 : "=r"(r[0]), "=r"(r[1]), "=r"(r[2]), "=r"(r[3]) : "r"(saddr));
}

// ---------------------------------------------------------------------------
// Kernel 1: tok = x + PE (bf16). Coalesced both sides.
// ---------------------------------------------------------------------------
__global__ __launch_bounds__(256) void pe_tok_kernel(const float* __restrict__ x) {
    int n_lo   = threadIdx.x & 31;
    int oct_lo = threadIdx.x >> 5;
    int n_hi   = blockIdx.x & 127;
    int oct_hi = (blockIdx.x >> 7) & 3;
    int b = blockIdx.x >> 9;

    int n = n_hi * 32 + n_lo;
    int ch0 = (oct_hi * 8 + oct_lo) * 8;
    int yy = n >> 6;
    int xx = n & 63;

    __nv_bfloat16 vh[8];
#pragma unroll
    for (int j = 0; j < 8; j++) {
        int ch = ch0 + j;
        int i, pos;
        if (ch < 128) { i = ch >> 1;         pos = xx; }
        else          { i = (ch - 128) >> 1; pos = yy; }
        float div = __expf(-(float)(2 * i) * (9.210340371976184f / 128.0f));
        float arg = (float)pos * div;
        float pe  = (ch & 1) ? cosf(arg) : sinf(arg);
        vh[j] = __float2bfloat16(x[((size_t)(b * CDIM + ch)) * NTOK + n] + pe);
    }
    *(uint4*)&g_tok[((size_t)(b * NTOK) + n) * CDIM + ch0] = *(uint4*)vh;
}

// ---------------------------------------------------------------------------
// Kernel 2: split Wq/Wk/Wv/Wo into bf16 hi/lo and gather all biases.
// ---------------------------------------------------------------------------
__global__ __launch_bounds__(256) void split_w_kernel(const float* __restrict__ Wq,
                                                      const float* __restrict__ Wk,
                                                      const float* __restrict__ Wv,
                                                      const float* __restrict__ Wo,
                                                      const float* __restrict__ bq,
                                                      const float* __restrict__ bk,
                                                      const float* __restrict__ bv,
                                                      const float* __restrict__ bo) {
    int t = blockIdx.x * 256 + threadIdx.x;      // 0..65535
    int idx4 = t * 4;
    int w = idx4 >> 16;                          // 0..3
    const float* src = (w == 0) ? Wq : (w == 1) ? Wk : (w == 2) ? Wv : Wo;
    float4 v = *(const float4*)&src[idx4 & 65535];
    __nv_bfloat16 h[4], l[4];
    split_bf16(v.x, h[0], l[0]); split_bf16(v.y, h[1], l[1]);
    split_bf16(v.z, h[2], l[2]); split_bf16(v.w, h[3], l[3]);
    if (w < 3) {
        *(uint2*)&g_wqkv_hi[idx4] = *(uint2*)h;
        *(uint2*)&g_wqkv_lo[idx4] = *(uint2*)l;
    } else {
        *(uint2*)&g_wo_hi[idx4 & 65535] = *(uint2*)h;
        *(uint2*)&g_wo_lo[idx4 & 65535] = *(uint2*)l;
    }
    if (t < 1024) {
        int which = t >> 8;
        const float* bsrc = (which == 0) ? bq : (which == 1) ? bk : (which == 2) ? bv : bo;
        g_bias[t] = bsrc[t & 255];
    }
}

// ---------------------------------------------------------------------------
// Fused QKV GEMM: C = tok(bf16) @ (Wh + Wl)^T + bias  (proven R7 kernel).
// ---------------------------------------------------------------------------
#define GPAD 40

__global__ __launch_bounds__(256) void qkv_mma_kernel() {
    __shared__ __align__(16) __nv_bfloat16 As[2][128][GPAD];
    __shared__ __align__(16) __nv_bfloat16 BsH[2][64][GPAD];
    __shared__ __align__(16) __nv_bfloat16 BsL[2][64][GPAD];

    int tid  = threadIdx.x;
    int warp = tid >> 5;
    int lane = tid & 31;
    int wm   = warp >> 1;
    int wn   = warp & 1;
    int g    = lane >> 2;
    int tig  = lane & 3;
    int m0 = blockIdx.x * 128;
    int w  = blockIdx.y >> 2;
    int o0 = (blockIdx.y & 3) * 64;
    size_t w_off = (size_t)w * 65536 + (size_t)o0 * CDIM;

    float c[2][4][4] = {};

    auto stage = [&](int s, int k0) {
#pragma unroll
        for (int i = 0; i < 2; i++) {
            int idx = tid * 2 + i;
            int row = idx >> 2, c8 = (idx & 3) * 8;
            cp_async16(&As[s][row][c8], g_tok + (size_t)(m0 + row) * CDIM + k0 + c8);
        }
        {
            int row = tid >> 2, c8 = (tid & 3) * 8;
            size_t go = w_off + (size_t)row * CDIM + k0 + c8;
            cp_async16(&BsH[s][row][c8], g_wqkv_hi + go);
            cp_async16(&BsL[s][row][c8], g_wqkv_lo + go);
        }
        cp_commit();
    };

    stage(0, 0);

#pragma unroll
    for (int it = 0; it < 8; it++) {
        int s = it & 1;
        asm volatile("cp.async.wait_group 0;\n");
        __syncthreads();
        if (it < 7) stage(s ^ 1, (it + 1) * 32);

        unsigned af[2][2][4];
        unsigned bfH[4][2][2], bfL[4][2][2];
#pragma unroll
        for (int mt = 0; mt < 2; mt++) {
            int r = wm * 32 + mt * 16 + g;
            const unsigned* h0 = (const unsigned*)&As[s][r][0];
            const unsigned* h1 = (const unsigned*)&As[s][r + 8][0];
#pragma unroll
            for (int kc = 0; kc < 2; kc++) {
                af[mt][kc][0] = h0[kc * 8 + tig];
                af[mt][kc][1] = h1[kc * 8 + tig];
                af[mt][kc][2] = h0[kc * 8 + tig + 4];
                af[mt][kc][3] = h1[kc * 8 + tig + 4];
            }
        }
#pragma unroll
        for (int nt = 0; nt < 4; nt++) {
            int r = wn * 32 + nt * 8 + g;
            const unsigned* rh = (const unsigned*)&BsH[s][r][0];
            const unsigned* rl = (const unsigned*)&BsL[s][r][0];
#pragma unroll
            for (int kc = 0; kc < 2; kc++) {
                bfH[nt][kc][0] = rh[kc * 8 + tig];
                bfH[nt][kc][1] = rh[kc * 8 + tig + 4];
                bfL[nt][kc][0] = rl[kc * 8 + tig];
                bfL[nt][kc][1] = rl[kc * 8 + tig + 4];
            }
        }

#pragma unroll
        for (int mt = 0; mt < 2; mt++)
#pragma unroll
            for (int nt = 0; nt < 4; nt++)
#pragma unroll
                for (int kc = 0; kc < 2; kc++) {
                    mma16816(c[mt][nt], af[mt][kc], bfH[nt][kc]);
                    mma16816(c[mt][nt], af[mt][kc], bfL[nt][kc]);
                }
    }

#pragma unroll
    for (int mt = 0; mt < 2; mt++) {
        int row0 = m0 + wm * 32 + mt * 16 + g;
#pragma unroll
        for (int nt = 0; nt < 4; nt++) {
            int o  = o0 + wn * 32 + nt * 8 + 2 * tig;
            float b0 = g_bias[w * 256 + o];
            float b1 = g_bias[w * 256 + o + 1];
#pragma unroll
            for (int half = 0; half < 2; half++) {
                int row = row0 + half * 8;
                int b = row >> 12;
                int n = row & 4095;
                float v0 = c[mt][nt][2 * half + 0] + b0;
                float v1 = c[mt][nt][2 * half + 1] + b1;
                if (w == 0) {
                    *(unsigned*)&g_q[(((size_t)(b * HEADS + (o >> 5))) * NTOK + n) * DK + (o & 31)] =
                        pack_bf16(v0 * QSCALE, v1 * QSCALE);
                } else if (w == 1) {
                    *(unsigned*)&g_k[(((size_t)(b * HEADS + (o >> 5))) * NTOK + n) * DK + (o & 31)] =
                        pack_bf16(v0, v1);
                } else {
                    __nv_bfloat16* base = g_vt +
                        ((size_t)(b * HEADS + (o >> 5))) * DK * NTOK + n;
                    base[(size_t)(o & 31) * NTOK]       = __float2bfloat16(v0);
                    base[(size_t)((o & 31) + 1) * NTOK] = __float2bfloat16(v1);
                }
            }
        }
    }
}

// ---------------------------------------------------------------------------
// Output projection: 3-term split-bf16 (proven R10 kernel).
// ---------------------------------------------------------------------------
__global__ __launch_bounds__(256) void gemm_o_kernel(float* __restrict__ Cout) {
    __shared__ __align__(16) __nv_bfloat16 AsH[2][128][GPAD];
    __shared__ __align__(16) __nv_bfloat16 AsL[2][128][GPAD];
    __shared__ __align__(16) __nv_bfloat16 BsH[2][64][GPAD];
    __shared__ __align__(16) __nv_bfloat16 BsL[2][64][GPAD];

    int tid  = threadIdx.x;
    int warp = tid >> 5;
    int lane = tid & 31;
    int wm   = warp >> 1;
    int wn   = warp & 1;
    int g    = lane >> 2;
    int tig  = lane & 3;
    int m0 = blockIdx.x * 128;
    int o0 = blockIdx.y * 64;

    float c[2][4][4] = {};

    auto stage = [&](int s, int k0) {
#pragma unroll
        for (int i = 0; i < 2; i++) {
            int idx = tid * 2 + i;
            int row = idx >> 2, c8 = (idx & 3) * 8;
            size_t ao = (size_t)(m0 + row) * CDIM + k0 + c8;
            cp_async16(&AsH[s][row][c8], g_att_hi + ao);
            cp_async16(&AsL[s][row][c8], g_att_lo + ao);
        }
        {
            int row = tid >> 2, c8 = (tid & 3) * 8;
            size_t go = (size_t)(o0 + row) * CDIM + k0 + c8;
            cp_async16(&BsH[s][row][c8], g_wo_hi + go);
            cp_async16(&BsL[s][row][c8], g_wo_lo + go);
        }
        cp_commit();
    };

    stage(0, 0);

#pragma unroll
    for (int it = 0; it < 8; it++) {
        int s = it & 1;
        asm volatile("cp.async.wait_group 0;\n");
        __syncthreads();
        if (it < 7) stage(s ^ 1, (it + 1) * 32);

        unsigned afH[2][2][4], afL[2][2][4];
        unsigned bfH[4][2][2], bfL[4][2][2];
#pragma unroll
        for (int mt = 0; mt < 2; mt++) {
            int r = wm * 32 + mt * 16 + g;
            const unsigned* h0 = (const unsigned*)&AsH[s][r][0];
            const unsigned* h1 = (const unsigned*)&AsH[s][r + 8][0];
            const unsigned* l0 = (const unsigned*)&AsL[s][r][0];
            const unsigned* l1 = (const unsigned*)&AsL[s][r + 8][0];
#pragma unroll
            for (int kc = 0; kc < 2; kc++) {
                afH[mt][kc][0] = h0[kc * 8 + tig];
                afH[mt][kc][1] = h1[kc * 8 + tig];
                afH[mt][kc][2] = h0[kc * 8 + tig + 4];
                afH[mt][kc][3] = h1[kc * 8 + tig + 4];
                afL[mt][kc][0] = l0[kc * 8 + tig];
                afL[mt][kc][1] = l1[kc * 8 + tig];
                afL[mt][kc][2] = l0[kc * 8 + tig + 4];
                afL[mt][kc][3] = l1[kc * 8 + tig + 4];
            }
        }
#pragma unroll
        for (int nt = 0; nt < 4; nt++) {
            int r = wn * 32 + nt * 8 + g;
            const unsigned* rh = (const unsigned*)&BsH[s][r][0];
            const unsigned* rl = (const unsigned*)&BsL[s][r][0];
#pragma unroll
            for (int kc = 0; kc < 2; kc++) {
                bfH[nt][kc][0] = rh[kc * 8 + tig];
                bfH[nt][kc][1] = rh[kc * 8 + tig + 4];
                bfL[nt][kc][0] = rl[kc * 8 + tig];
                bfL[nt][kc][1] = rl[kc * 8 + tig + 4];
            }
        }

#pragma unroll
        for (int mt = 0; mt < 2; mt++)
#pragma unroll
            for (int nt = 0; nt < 4; nt++)
#pragma unroll
                for (int kc = 0; kc < 2; kc++) {
                    mma16816(c[mt][nt], afH[mt][kc], bfH[nt][kc]);
                    mma16816(c[mt][nt], afH[mt][kc], bfL[nt][kc]);
                    mma16816(c[mt][nt], afL[mt][kc], bfH[nt][kc]);
                }
    }

#pragma unroll
    for (int mt = 0; mt < 2; mt++) {
        int row0 = m0 + wm * 32 + mt * 16 + g;
#pragma unroll
        for (int nt = 0; nt < 4; nt++) {
            int o  = o0 + wn * 32 + nt * 8 + 2 * tig;
            float b0 = g_bias[768 + o];
            float b1 = g_bias[768 + o + 1];
#pragma unroll
            for (int half = 0; half < 2; half++) {
                int row = row0 + half * 8;
                int b = row >> 12;
                int n = row & 4095;
                float* base = Cout + (size_t)b * CDIM * NTOK + n;
                base[(size_t)o * NTOK]       = c[mt][nt][2 * half + 0] + b0;
                base[(size_t)(o + 1) * NTOK] = c[mt][nt][2 * half + 1] + b1;
            }
        }
    }
}

// ---------------------------------------------------------------------------
// Flash attention v4: 256 thr / 8 warps, warp owns 32 q-rows (2 m-tiles),
// BR=256, BC=64. K-frag ldsm shared across m-tiles; V-frag ldsm feeds 8 MMAs
// on independent accumulators. Halves smem frag traffic per q-row (the
// measured bottleneck: L1=67%).
// ---------------------------------------------------------------------------
#define BR 256
#define BC 64
#define KPAD 40
#define VPAD 72
#define ONES_BF16X2 0x3F803F80u

__global__ __launch_bounds__(256, 2) void flash_mma_kernel() {
    __shared__ __align__(16) __nv_bfloat16 Ks[2][BC][KPAD];
    __shared__ __align__(16) __nv_bfloat16 Vs[2][DK][VPAD];

    int bh    = blockIdx.y;
    int qbase = blockIdx.x * BR;
    int tid   = threadIdx.x;
    int warp  = tid >> 5;
    int lane  = tid & 31;
    int g     = lane >> 2;
    int tig   = lane & 3;

    const __nv_bfloat16* qb = g_q  + (size_t)bh * NTOK * DK;
    const __nv_bfloat16* kb = g_k  + (size_t)bh * NTOK * DK;
    const __nv_bfloat16* vb = g_vt + (size_t)bh * DK * NTOK;

    int kr = tid >> 2, kq = tid & 3;
    int vd = tid >> 3, vq = tid & 7;

    auto stage_load = [&](int s, int n0) {
        cp_async16(&Ks[s][kr][kq * 8], kb + (size_t)(n0 + kr) * DK + kq * 8);
        cp_async16(&Vs[s][vd][vq * 8], vb + (size_t)vd * NTOK + n0 + vq * 8);
        cp_commit();
    };

    int lmr = lane & 7, lmc = lane >> 3;
    unsigned ks_smem = (unsigned)__cvta_generic_to_shared(&Ks[0][0][0])
                     + (unsigned)(lmr * (KPAD * 2) + lmc * 16);
    unsigned vs_smem = (unsigned)__cvta_generic_to_shared(&Vs[0][0][0])
                     + (unsigned)(lmr * (VPAD * 2) + lmc * 16);

    // Q fragments: 2 m-tiles of 16 rows
    unsigned qf[2][2][4];
#pragma unroll
    for (int mt = 0; mt < 2; mt++) {
        int r0 = qbase + warp * 32 + mt * 16 + g;
        const unsigned* q0 = (const unsigned*)(qb + (size_t)r0 * DK);
        const unsigned* q1 = (const unsigned*)(qb + (size_t)(r0 + 8) * DK);
#pragma unroll
        for (int cc = 0; cc < 2; cc++) {
            qf[mt][cc][0] = q0[8 * cc + tig];
            qf[mt][cc][1] = q1[8 * cc + tig];
            qf[mt][cc][2] = q0[8 * cc + tig + 4];
            qf[mt][cc][3] = q1[8 * cc + tig + 4];
        }
    }

    float O[2][4][4] = {};
    float lacc[2][4] = {};
    const unsigned onesb[2] = {ONES_BF16X2, ONES_BF16X2};

    stage_load(0, 0);

    const int NT = NTOK / BC;
    for (int it = 0; it < NT; it++) {
        int s = it & 1;
        asm volatile("cp.async.wait_group 0;\n");
        __syncthreads();
        if (it + 1 < NT) stage_load(s ^ 1, (it + 1) * BC);

        unsigned ksb = ks_smem + (unsigned)(s * BC * KPAD * 2);
        unsigned vsb = vs_smem + (unsigned)(s * DK * VPAD * 2);

        // QK: one ldsm per t feeds both m-tiles (4 MMAs); exp2 fused.
        unsigned Pf[2][4][4];
#pragma unroll
        for (int t = 0; t < 8; t++) {
            unsigned kf[4];
            ldsm4(kf, ksb + (unsigned)(t * 8 * KPAD * 2));
            float Sa[4] = {0.0f, 0.0f, 0.0f, 0.0f};
            float Sb[4] = {0.0f, 0.0f, 0.0f, 0.0f};
            mma16816(Sa, qf[0][0], &kf[0]);
            mma16816(Sb, qf[1][0], &kf[0]);
            mma16816(Sa, qf[0][1], &kf[2]);
            mma16816(Sb, qf[1][1], &kf[2]);
            Pf[0][t >> 1][(t & 1) * 2 + 0] = ex2_bf16x2(pack_bf16(Sa[0], Sa[1]));
            Pf[0][t >> 1][(t & 1) * 2 + 1] = ex2_bf16x2(pack_bf16(Sa[2], Sa[3]));
            Pf[1][t >> 1][(t & 1) * 2 + 0] = ex2_bf16x2(pack_bf16(Sb[0], Sb[1]));
            Pf[1][t >> 1][(t & 1) * 2 + 1] = ex2_bf16x2(pack_bf16(Sb[2], Sb[3]));
        }

        // PV: V-frags loaded once per dt, 8 MMAs alternating independent accs.
#pragma unroll
        for (int dt = 0; dt < 4; dt++) {
            unsigned vf[8];
            unsigned va = vsb + (unsigned)(dt * 8 * VPAD * 2);
            ldsm4(&vf[0], va);
            ldsm4(&vf[4], va + 64);
#pragma unroll
            for (int kc = 0; kc < 4; kc++) {
                mma16816(O[0][dt], Pf[0][kc], &vf[kc * 2]);
                mma16816(O[1][dt], Pf[1][kc], &vf[kc * 2]);
            }
        }
#pragma unroll
        for (int kc = 0; kc < 4; kc++) {
            mma16816(lacc[0], Pf[0][kc], onesb);
            mma16816(lacc[1], Pf[1][kc], onesb);
        }
    }

    int b = bh >> 3, h = bh & 7;
#pragma unroll
    for (int mt = 0; mt < 2; mt++) {
        float inv0 = 1.0f / lacc[mt][0];
        float inv1 = 1.0f / lacc[mt][2];
        int row0 = qbase + warp * 32 + mt * 16 + g;
        size_t o0off = ((size_t)(b * NTOK + row0) * CDIM) + h * DK;
        size_t o1off = ((size_t)(b * NTOK + row0 + 8) * CDIM) + h * DK;
#pragma unroll
        for (int dt = 0; dt < 4; dt++) {
            int d = 8 * dt + 2 * tig;
            float a0 = O[mt][dt][0] * inv0, a1 = O[mt][dt][1] * inv0;
            float b0 = O[mt][dt][2] * inv1, b1 = O[mt][dt][3] * inv1;
            __nv_bfloat16 h0, l0b, h1, l1b;
            split_bf16(a0, h0, l0b); split_bf16(a1, h1, l1b);
            *(unsigned*)&g_att_hi[o0off + d] = pack_bf16(__bfloat162float(h0), __bfloat162float(h1));
            *(unsigned*)&g_att_lo[o0off + d] = pack_bf16(__bfloat162float(l0b), __bfloat162float(l1b));
            split_bf16(b0, h0, l0b); split_bf16(b1, h1, l1b);
            *(unsigned*)&g_att_hi[o1off + d] = pack_bf16(__bfloat162float(h0), __bfloat162float(h1));
            *(unsigned*)&g_att_lo[o1off + d] = pack_bf16(__bfloat162float(l0b), __bfloat162float(l1b));
        }
    }
}

// ---------------------------------------------------------------------------
extern "C" void kernel_launch(void* const* d_in, const int* in_sizes, int n_in,
                              void* d_out, int out_size) {
    const float* x  = (const float*)d_in[0];
    const float* Wq = (const float*)d_in[1];
    const float* bq = (const float*)d_in[2];
    const float* Wk = (const float*)d_in[3];
    const float* bk = (const float*)d_in[4];
    const float* Wv = (const float*)d_in[5];
    const float* bv = (const float*)d_in[6];
    const float* Wo = (const float*)d_in[7];
    const float* bo = (const float*)d_in[8];
    float* out = (float*)d_out;

    pe_tok_kernel<<<1024, 256>>>(x);
    split_w_kernel<<<256, 256>>>(Wq, Wk, Wv, Wo, bq, bk, bv, bo);

    qkv_mma_kernel<<<dim3(MROWS / 128, 12), 256>>>();

    flash_mma_kernel<<<dim3(NTOK / BR, BATCH * HEADS), 256>>>();

    gemm_o_kernel<<<dim3(MROWS / 128, CDIM / 64), 256>>>(out);
}